// round 1
// baseline (speedup 1.0000x reference)
#include <cuda_runtime.h>
#include <cuda_bf16.h>

#define D_MODEL 768
#define NTOK 4096           // B*S = 2*2048
#define SEQ 2048
#define NHEAD 12
#define HDIM 64
#define LORA_R 16
#define LORA_SCALE 4.0f     // U * alpha/sqrt(R) = 1.0 * 16/4

// ---------------- scratch (device globals: no allocation allowed) ----------
__device__ float g_Mq[D_MODEL * D_MODEL];
__device__ float g_Mk[D_MODEL * D_MODEL];
__device__ float g_Mv[D_MODEL * D_MODEL];
__device__ float g_Mo[D_MODEL * D_MODEL];
__device__ float g_q[NTOK * D_MODEL];
__device__ float g_k[NTOK * D_MODEL];
__device__ float g_v[NTOK * D_MODEL];
__device__ float g_ao[NTOK * D_MODEL];

// ---------------- build effective weight: M[i][j] = W[j][i] + s*<A[i],A[j]> -
__global__ void build_weight_kernel(const float* __restrict__ W,
                                    const float* __restrict__ A,
                                    float scale,
                                    float* __restrict__ M) {
    int idx = blockIdx.x * blockDim.x + threadIdx.x;
    if (idx >= D_MODEL * D_MODEL) return;
    int i = idx / D_MODEL;
    int j = idx - i * D_MODEL;
    float acc = W[j * D_MODEL + i];
    if (scale != 0.0f) {
        float s = 0.0f;
#pragma unroll
        for (int r = 0; r < LORA_R; r++)
            s += A[i * LORA_R + r] * A[j * LORA_R + r];
        acc += scale * s;
    }
    M[idx] = acc;
}

// ---------------- SGEMM: Y[m][n] = sum_k X[m][k]*Mw[k][n] + bias[n] ---------
// Fixed N = K = 768. BM=BN=128, BK=8, 256 threads, 8x8 per thread.
__global__ __launch_bounds__(256) void sgemm_bias_kernel(
    const float* __restrict__ X, const float* __restrict__ Mw,
    const float* __restrict__ bias, float* __restrict__ Y) {
    const int N = D_MODEL, K = D_MODEL;
    __shared__ float As[8][128];   // [k][m]
    __shared__ float Bs[8][128];   // [k][n]

    int tid  = threadIdx.x;
    int brow = blockIdx.y * 128;
    int bcol = blockIdx.x * 128;
    int tr = tid >> 4;          // 0..15
    int tc = tid & 15;          // 0..15

    // load mapping
    int am = tid >> 1;          // 0..127 (row within tile)
    int ak = (tid & 1) * 4;     // 0 or 4
    int bk = tid >> 5;          // 0..7
    int bn = (tid & 31) * 4;    // 0..124

    float acc[8][8];
#pragma unroll
    for (int i = 0; i < 8; i++)
#pragma unroll
        for (int j = 0; j < 8; j++) acc[i][j] = 0.0f;

    for (int k0 = 0; k0 < K; k0 += 8) {
        float4 av = *reinterpret_cast<const float4*>(&X[(size_t)(brow + am) * K + k0 + ak]);
        As[ak + 0][am] = av.x;
        As[ak + 1][am] = av.y;
        As[ak + 2][am] = av.z;
        As[ak + 3][am] = av.w;
        *reinterpret_cast<float4*>(&Bs[bk][bn]) =
            *reinterpret_cast<const float4*>(&Mw[(size_t)(k0 + bk) * N + bcol + bn]);
        __syncthreads();

#pragma unroll
        for (int kk = 0; kk < 8; kk++) {
            float4 a0 = *reinterpret_cast<const float4*>(&As[kk][tr * 8]);
            float4 a1 = *reinterpret_cast<const float4*>(&As[kk][tr * 8 + 4]);
            float4 b0 = *reinterpret_cast<const float4*>(&Bs[kk][tc * 8]);
            float4 b1 = *reinterpret_cast<const float4*>(&Bs[kk][tc * 8 + 4]);
            float af[8] = {a0.x, a0.y, a0.z, a0.w, a1.x, a1.y, a1.z, a1.w};
            float bf[8] = {b0.x, b0.y, b0.z, b0.w, b1.x, b1.y, b1.z, b1.w};
#pragma unroll
            for (int i = 0; i < 8; i++)
#pragma unroll
                for (int j = 0; j < 8; j++) acc[i][j] += af[i] * bf[j];
        }
        __syncthreads();
    }

#pragma unroll
    for (int i = 0; i < 8; i++) {
        size_t row = brow + tr * 8 + i;
#pragma unroll
        for (int j = 0; j < 8; j += 4) {
            int col = bcol + tc * 8 + j;
            float4 o;
            o.x = acc[i][j + 0] + bias[col + 0];
            o.y = acc[i][j + 1] + bias[col + 1];
            o.z = acc[i][j + 2] + bias[col + 2];
            o.w = acc[i][j + 3] + bias[col + 3];
            *reinterpret_cast<float4*>(&Y[row * N + col]) = o;
        }
    }
}

// ---------------- attention: flash-style, 64-query tiles -------------------
// grid: (32 q-tiles, 24 b*h), 256 threads.
// smem: Qs[64][64], Kt[64][65] (transposed, padded), Vs[64][64], Ss[64][65]
#define ATT_SMEM ((4096 + 65 * 64 + 4096 + 65 * 64) * 4)

__global__ __launch_bounds__(256) void attn_kernel(
    const float* __restrict__ q, const float* __restrict__ k,
    const float* __restrict__ v, float* __restrict__ o) {
    extern __shared__ float sm[];
    float* Qs = sm;                 // [64][64]
    float* Kt = sm + 4096;          // [d][key], stride 65
    float* Vs = sm + 4096 + 65 * 64; // [64][64]
    float* Ss = Vs + 4096;          // [64][65]

    int qt = blockIdx.x;            // 0..31
    int bh = blockIdx.y;            // 0..23
    int b = bh / NHEAD;
    int h = bh - b * NHEAD;
    size_t base = (size_t)b * SEQ * D_MODEL + (size_t)h * HDIM;

    int tid = threadIdx.x;
    int lr = tid >> 2;              // 0..63 (row for loads / softmax)
    int lc = (tid & 3) * 16;        // 0,16,32,48

    // load Q tile
    {
        const float* src = q + base + (size_t)(qt * 64 + lr) * D_MODEL + lc;
        float4* dst = reinterpret_cast<float4*>(&Qs[lr * 64 + lc]);
#pragma unroll
        for (int i = 0; i < 4; i++)
            dst[i] = reinterpret_cast<const float4*>(src)[i];
    }

    float m = -1e30f, l = 0.0f;
    float oacc[16];
#pragma unroll
    for (int i = 0; i < 16; i++) oacc[i] = 0.0f;

    int sr = (tid >> 4) * 4;        // score rows (4)
    int sc = (tid & 15) * 4;        // score cols (4)

    for (int kt0 = 0; kt0 < SEQ; kt0 += 64) {
        // load K (transposed into Kt) and V tiles
        {
            const float* ksrc = k + base + (size_t)(kt0 + lr) * D_MODEL + lc;
            const float* vsrc = v + base + (size_t)(kt0 + lr) * D_MODEL + lc;
            float4* vdst = reinterpret_cast<float4*>(&Vs[lr * 64 + lc]);
#pragma unroll
            for (int i = 0; i < 4; i++) {
                float4 kv = reinterpret_cast<const float4*>(ksrc)[i];
                int c0 = lc + i * 4;
                Kt[(c0 + 0) * 65 + lr] = kv.x;
                Kt[(c0 + 1) * 65 + lr] = kv.y;
                Kt[(c0 + 2) * 65 + lr] = kv.z;
                Kt[(c0 + 3) * 65 + lr] = kv.w;
                vdst[i] = reinterpret_cast<const float4*>(vsrc)[i];
            }
        }
        __syncthreads();

        // scores: 4x4 per thread, S = Q K^T * 1/8
        {
            float sacc[4][4];
#pragma unroll
            for (int i = 0; i < 4; i++)
#pragma unroll
                for (int j = 0; j < 4; j++) sacc[i][j] = 0.0f;
#pragma unroll 4
            for (int d = 0; d < 64; d++) {
                float qa[4], kb[4];
#pragma unroll
                for (int i = 0; i < 4; i++) qa[i] = Qs[(sr + i) * 64 + d];
#pragma unroll
                for (int j = 0; j < 4; j++) kb[j] = Kt[d * 65 + sc + j];
#pragma unroll
                for (int i = 0; i < 4; i++)
#pragma unroll
                    for (int j = 0; j < 4; j++) sacc[i][j] += qa[i] * kb[j];
            }
#pragma unroll
            for (int i = 0; i < 4; i++)
#pragma unroll
                for (int j = 0; j < 4; j++)
                    Ss[(sr + i) * 65 + sc + j] = sacc[i][j] * 0.125f;
        }
        __syncthreads();

        // online softmax + PV. r = lr, cols lc..lc+15
        {
            float tmax = -1e30f;
#pragma unroll 8
            for (int j = 0; j < 64; j++) tmax = fmaxf(tmax, Ss[lr * 65 + j]);
            float newm = fmaxf(m, tmax);
            float alpha = __expf(m - newm);
            m = newm;
            l *= alpha;
#pragma unroll
            for (int i = 0; i < 16; i++) oacc[i] *= alpha;
#pragma unroll 2
            for (int j = 0; j < 64; j++) {
                float p = __expf(Ss[lr * 65 + j] - newm);
                l += p;
                const float4* v4 = reinterpret_cast<const float4*>(&Vs[j * 64 + lc]);
#pragma unroll
                for (int i = 0; i < 4; i++) {
                    float4 vv = v4[i];
                    oacc[i * 4 + 0] += p * vv.x;
                    oacc[i * 4 + 1] += p * vv.y;
                    oacc[i * 4 + 2] += p * vv.z;
                    oacc[i * 4 + 3] += p * vv.w;
                }
            }
        }
        __syncthreads();
    }

    float inv = 1.0f / l;
    float* dst = o + base + (size_t)(qt * 64 + lr) * D_MODEL + lc;
#pragma unroll
    for (int i = 0; i < 4; i++) {
        float4 ov;
        ov.x = oacc[i * 4 + 0] * inv;
        ov.y = oacc[i * 4 + 1] * inv;
        ov.z = oacc[i * 4 + 2] * inv;
        ov.w = oacc[i * 4 + 3] * inv;
        reinterpret_cast<float4*>(dst)[i] = ov;
    }
}

// ---------------- launch ---------------------------------------------------
extern "C" void kernel_launch(void* const* d_in, const int* in_sizes, int n_in,
                              void* d_out, int out_size) {
    const float* query = (const float*)d_in[0];
    const float* key_  = (const float*)d_in[1];
    const float* value = (const float*)d_in[2];
    const float* Wq = (const float*)d_in[3];
    const float* bq = (const float*)d_in[4];
    const float* Aq = (const float*)d_in[5];
    const float* Wk = (const float*)d_in[6];
    const float* bk = (const float*)d_in[7];
    const float* Ak = (const float*)d_in[8];
    const float* Wv = (const float*)d_in[9];
    const float* bv = (const float*)d_in[10];
    const float* Av = (const float*)d_in[11];
    const float* Wo = (const float*)d_in[12];
    const float* bo = (const float*)d_in[13];
    float* out = (float*)d_out;

    float *pMq, *pMk, *pMv, *pMo, *pq, *pk, *pv, *pao;
    cudaGetSymbolAddress((void**)&pMq, g_Mq);
    cudaGetSymbolAddress((void**)&pMk, g_Mk);
    cudaGetSymbolAddress((void**)&pMv, g_Mv);
    cudaGetSymbolAddress((void**)&pMo, g_Mo);
    cudaGetSymbolAddress((void**)&pq, g_q);
    cudaGetSymbolAddress((void**)&pk, g_k);
    cudaGetSymbolAddress((void**)&pv, g_v);
    cudaGetSymbolAddress((void**)&pao, g_ao);

    cudaFuncSetAttribute(attn_kernel,
                         cudaFuncAttributeMaxDynamicSharedMemorySize, ATT_SMEM);

    // effective weights (folds SingLoRA delta into the GEMM weight)
    int nw = D_MODEL * D_MODEL;
    int gb = (nw + 255) / 256;
    build_weight_kernel<<<gb, 256>>>(Wq, Aq, LORA_SCALE, pMq);
    build_weight_kernel<<<gb, 256>>>(Wk, Ak, LORA_SCALE, pMk);
    build_weight_kernel<<<gb, 256>>>(Wv, Av, LORA_SCALE, pMv);
    build_weight_kernel<<<gb, 256>>>(Wo, Aq, 0.0f, pMo);   // plain transpose

    dim3 ggrid(D_MODEL / 128, NTOK / 128);   // (6, 32)
    sgemm_bias_kernel<<<ggrid, 256>>>(query, pMq, bq, pq);
    sgemm_bias_kernel<<<ggrid, 256>>>(key_,  pMk, bk, pk);
    sgemm_bias_kernel<<<ggrid, 256>>>(value, pMv, bv, pv);

    dim3 agrid(SEQ / 64, 2 * NHEAD);         // (32, 24)
    attn_kernel<<<agrid, 256, ATT_SMEM>>>(pq, pk, pv, pao);

    sgemm_bias_kernel<<<ggrid, 256>>>(pao, pMo, bo, out);
}

// round 2
// speedup vs baseline: 1.0630x; 1.0630x over previous
#include <cuda_runtime.h>
#include <cuda_bf16.h>

#define D_MODEL 768
#define NTOK 4096           // B*S = 2*2048
#define SEQ 2048
#define NHEAD 12
#define HDIM 64
#define LORA_R 16
#define LORA_SCALE 4.0f     // U * alpha/sqrt(R) = 1.0 * 16/4

typedef unsigned long long ull;

// ---------------- packed fp32x2 helpers (exact IEEE fp32, 2x rate) ---------
__device__ __forceinline__ ull pk2(float lo, float hi) {
    ull r;
    asm("mov.b64 %0, {%1, %2};" : "=l"(r)
        : "r"(__float_as_uint(lo)), "r"(__float_as_uint(hi)));
    return r;
}
__device__ __forceinline__ void fma2(ull& d, ull a, ull b) {
    asm("fma.rn.f32x2 %0, %1, %2, %0;" : "+l"(d) : "l"(a), "l"(b));
}
__device__ __forceinline__ void mul2(ull& d, ull a, ull b) {
    asm("mul.rn.f32x2 %0, %1, %2;" : "=l"(d) : "l"(a), "l"(b));
}
__device__ __forceinline__ float2 upk2(ull v) {
    unsigned lo, hi;
    asm("mov.b64 {%0, %1}, %2;" : "=r"(lo), "=r"(hi) : "l"(v));
    return make_float2(__uint_as_float(lo), __uint_as_float(hi));
}

// ---------------- scratch (device globals: no allocation allowed) ----------
__device__ float g_Mq[D_MODEL * D_MODEL];
__device__ float g_Mk[D_MODEL * D_MODEL];
__device__ float g_Mv[D_MODEL * D_MODEL];
__device__ float g_Mo[D_MODEL * D_MODEL];
__device__ float g_q[NTOK * D_MODEL];
__device__ float g_k[NTOK * D_MODEL];
__device__ float g_v[NTOK * D_MODEL];
__device__ float g_ao[NTOK * D_MODEL];

// ---------------- build effective weight: M[i][j] = W[j][i] + s*<A[i],A[j]> -
__global__ void build_weight_kernel(const float* __restrict__ W,
                                    const float* __restrict__ A,
                                    float scale,
                                    float* __restrict__ M) {
    int idx = blockIdx.x * blockDim.x + threadIdx.x;
    if (idx >= D_MODEL * D_MODEL) return;
    int i = idx / D_MODEL;
    int j = idx - i * D_MODEL;
    float acc = W[j * D_MODEL + i];
    if (scale != 0.0f) {
        float s = 0.0f;
#pragma unroll
        for (int r = 0; r < LORA_R; r++)
            s += A[i * LORA_R + r] * A[j * LORA_R + r];
        acc += scale * s;
    }
    M[idx] = acc;
}

// ---------------- SGEMM: Y = X*Mw + bias. N=K=768, BM=BN=128, BK=16 --------
// 256 threads, 8x8 per thread, f32x2 packed FMA, double-buffered smem.
__global__ __launch_bounds__(256, 2) void sgemm_bias_kernel(
    const float* __restrict__ X, const float* __restrict__ Mw,
    const float* __restrict__ bias, float* __restrict__ Y) {
    const int N = D_MODEL, K = D_MODEL;
    __shared__ float As[2][16][128];   // [buf][k][m]
    __shared__ float Bs[2][16][128];   // [buf][k][n]

    int tid  = threadIdx.x;
    int brow = blockIdx.y * 128;
    int bcol = blockIdx.x * 128;
    int tr = tid >> 4;           // 0..15
    int tc = tid & 15;           // 0..15

    // load mapping (BK=16)
    int am = tid >> 1;           // 0..127
    int ak = (tid & 1) * 8;      // 0 or 8
    int bk = tid >> 5;           // 0..7 (also handles bk+8)
    int bn = (tid & 31) * 4;     // 0..124

    const float* Xp  = X  + (size_t)(brow + am) * K + ak;
    const float* Bp0 = Mw + (size_t)bk * N + bcol + bn;
    const float* Bp1 = Mw + (size_t)(bk + 8) * N + bcol + bn;

    ull acc[8][4];
#pragma unroll
    for (int i = 0; i < 8; i++)
#pragma unroll
        for (int j = 0; j < 4; j++) acc[i][j] = 0ULL;

    // preload k0 = 0
    float4 a0v = *reinterpret_cast<const float4*>(Xp);
    float4 a1v = *reinterpret_cast<const float4*>(Xp + 4);
    float4 b0v = *reinterpret_cast<const float4*>(Bp0);
    float4 b1v = *reinterpret_cast<const float4*>(Bp1);
    As[0][ak + 0][am] = a0v.x; As[0][ak + 1][am] = a0v.y;
    As[0][ak + 2][am] = a0v.z; As[0][ak + 3][am] = a0v.w;
    As[0][ak + 4][am] = a1v.x; As[0][ak + 5][am] = a1v.y;
    As[0][ak + 6][am] = a1v.z; As[0][ak + 7][am] = a1v.w;
    *reinterpret_cast<float4*>(&Bs[0][bk][bn])     = b0v;
    *reinterpret_cast<float4*>(&Bs[0][bk + 8][bn]) = b1v;
    __syncthreads();

    int buf = 0;
    for (int k0 = 0; k0 < K; k0 += 16) {
        bool has = (k0 + 16) < K;
        if (has) {
            a0v = *reinterpret_cast<const float4*>(Xp + k0 + 16);
            a1v = *reinterpret_cast<const float4*>(Xp + k0 + 20);
            b0v = *reinterpret_cast<const float4*>(Bp0 + (size_t)(k0 + 16) * N);
            b1v = *reinterpret_cast<const float4*>(Bp1 + (size_t)(k0 + 16) * N);
        }
#pragma unroll
        for (int kk = 0; kk < 16; kk++) {
            float4 af0 = *reinterpret_cast<const float4*>(&As[buf][kk][tr * 8]);
            float4 af1 = *reinterpret_cast<const float4*>(&As[buf][kk][tr * 8 + 4]);
            float4 bf0 = *reinterpret_cast<const float4*>(&Bs[buf][kk][tc * 8]);
            float4 bf1 = *reinterpret_cast<const float4*>(&Bs[buf][kk][tc * 8 + 4]);
            ull bp0 = pk2(bf0.x, bf0.y), bp1 = pk2(bf0.z, bf0.w);
            ull bp2 = pk2(bf1.x, bf1.y), bp3 = pk2(bf1.z, bf1.w);
            float afs[8] = {af0.x, af0.y, af0.z, af0.w, af1.x, af1.y, af1.z, af1.w};
#pragma unroll
            for (int i = 0; i < 8; i++) {
                ull da = pk2(afs[i], afs[i]);
                fma2(acc[i][0], da, bp0);
                fma2(acc[i][1], da, bp1);
                fma2(acc[i][2], da, bp2);
                fma2(acc[i][3], da, bp3);
            }
        }
        if (has) {
            As[buf ^ 1][ak + 0][am] = a0v.x; As[buf ^ 1][ak + 1][am] = a0v.y;
            As[buf ^ 1][ak + 2][am] = a0v.z; As[buf ^ 1][ak + 3][am] = a0v.w;
            As[buf ^ 1][ak + 4][am] = a1v.x; As[buf ^ 1][ak + 5][am] = a1v.y;
            As[buf ^ 1][ak + 6][am] = a1v.z; As[buf ^ 1][ak + 7][am] = a1v.w;
            *reinterpret_cast<float4*>(&Bs[buf ^ 1][bk][bn])     = b0v;
            *reinterpret_cast<float4*>(&Bs[buf ^ 1][bk + 8][bn]) = b1v;
        }
        __syncthreads();
        buf ^= 1;
    }

#pragma unroll
    for (int i = 0; i < 8; i++) {
        size_t row = brow + tr * 8 + i;
        int col = bcol + tc * 8;
        float2 p0 = upk2(acc[i][0]), p1 = upk2(acc[i][1]);
        float2 p2 = upk2(acc[i][2]), p3 = upk2(acc[i][3]);
        float4 o0, o1;
        o0.x = p0.x + bias[col + 0]; o0.y = p0.y + bias[col + 1];
        o0.z = p1.x + bias[col + 2]; o0.w = p1.y + bias[col + 3];
        o1.x = p2.x + bias[col + 4]; o1.y = p2.y + bias[col + 5];
        o1.z = p3.x + bias[col + 6]; o1.w = p3.y + bias[col + 7];
        *reinterpret_cast<float4*>(&Y[row * N + col])     = o0;
        *reinterpret_cast<float4*>(&Y[row * N + col + 4]) = o1;
    }
}

// ---------------- attention: flash-style, 64-query tiles, f32x2 ------------
#define KT_STRIDE 68
#define SS_STRIDE 68
#define ATT_SMEM ((4096 + 64 * KT_STRIDE + 4096 + 64 * SS_STRIDE) * 4)

__global__ __launch_bounds__(256) void attn_kernel(
    const float* __restrict__ q, const float* __restrict__ k,
    const float* __restrict__ v, float* __restrict__ o) {
    extern __shared__ float sm[];
    float* Qs = sm;                       // [64][64], pre-scaled by 1/8
    float* Kt = sm + 4096;                // [d][key], stride 68
    float* Vs = Kt + 64 * KT_STRIDE;      // [64][64]
    float* Ss = Vs + 4096;                // [64][68]: scores, then p

    int qt = blockIdx.x;
    int bh = blockIdx.y;
    int b = bh / NHEAD;
    int h = bh - b * NHEAD;
    size_t base = (size_t)b * SEQ * D_MODEL + (size_t)h * HDIM;

    int tid = threadIdx.x;
    int lr = tid >> 2;               // 0..63: row for softmax/PV/load
    int lc = (tid & 3) * 16;         // 0,16,32,48: col segment
    int sr = (tid >> 4) * 4;         // score rows
    int sc = (tid & 15) * 4;         // score cols

    // load Q tile (folding 1/sqrt(hd) = 0.125)
    {
        const float* src = q + base + (size_t)(qt * 64 + lr) * D_MODEL + lc;
        float4* dst = reinterpret_cast<float4*>(&Qs[lr * 64 + lc]);
#pragma unroll
        for (int i = 0; i < 4; i++) {
            float4 qv = reinterpret_cast<const float4*>(src)[i];
            qv.x *= 0.125f; qv.y *= 0.125f; qv.z *= 0.125f; qv.w *= 0.125f;
            dst[i] = qv;
        }
    }

    float m = -1e30f, l = 0.0f;
    ull oacc[8];
#pragma unroll
    for (int i = 0; i < 8; i++) oacc[i] = 0ULL;

    for (int kt0 = 0; kt0 < SEQ; kt0 += 64) {
        // load K (transposed) and V
        {
            const float* ksrc = k + base + (size_t)(kt0 + lr) * D_MODEL + lc;
            const float* vsrc = v + base + (size_t)(kt0 + lr) * D_MODEL + lc;
            float4* vdst = reinterpret_cast<float4*>(&Vs[lr * 64 + lc]);
#pragma unroll
            for (int i = 0; i < 4; i++) {
                float4 kv = reinterpret_cast<const float4*>(ksrc)[i];
                int c0 = lc + i * 4;
                Kt[(c0 + 0) * KT_STRIDE + lr] = kv.x;
                Kt[(c0 + 1) * KT_STRIDE + lr] = kv.y;
                Kt[(c0 + 2) * KT_STRIDE + lr] = kv.z;
                Kt[(c0 + 3) * KT_STRIDE + lr] = kv.w;
                vdst[i] = reinterpret_cast<const float4*>(vsrc)[i];
            }
        }
        __syncthreads();

        // scores: 4 rows x 4 cols per thread, packed over cols
        {
            ull sacc[4][2];
#pragma unroll
            for (int i = 0; i < 4; i++) { sacc[i][0] = 0ULL; sacc[i][1] = 0ULL; }
#pragma unroll 2
            for (int d0 = 0; d0 < 64; d0 += 4) {
                float4 qv[4];
#pragma unroll
                for (int i = 0; i < 4; i++)
                    qv[i] = *reinterpret_cast<const float4*>(&Qs[(sr + i) * 64 + d0]);
#pragma unroll
                for (int dd = 0; dd < 4; dd++) {
                    float4 kb = *reinterpret_cast<const float4*>(&Kt[(d0 + dd) * KT_STRIDE + sc]);
                    ull b01 = pk2(kb.x, kb.y);
                    ull b23 = pk2(kb.z, kb.w);
#pragma unroll
                    for (int i = 0; i < 4; i++) {
                        float qa = (dd == 0) ? qv[i].x : (dd == 1) ? qv[i].y
                                 : (dd == 2) ? qv[i].z : qv[i].w;
                        ull da = pk2(qa, qa);
                        fma2(sacc[i][0], da, b01);
                        fma2(sacc[i][1], da, b23);
                    }
                }
            }
#pragma unroll
            for (int i = 0; i < 4; i++) {
                float2 s0 = upk2(sacc[i][0]);
                float2 s1 = upk2(sacc[i][1]);
                float4 so = make_float4(s0.x, s0.y, s1.x, s1.y);
                *reinterpret_cast<float4*>(&Ss[(sr + i) * SS_STRIDE + sc]) = so;
            }
        }
        __syncthreads();

        // online softmax: quad (4 lanes) shares row lr, each handles 16 cols
        {
            float* srow = &Ss[lr * SS_STRIDE + lc];
            float rmax = -1e30f;
#pragma unroll
            for (int jj = 0; jj < 16; jj += 4) {
                float4 s = *reinterpret_cast<const float4*>(&srow[jj]);
                rmax = fmaxf(rmax, fmaxf(fmaxf(s.x, s.y), fmaxf(s.z, s.w)));
            }
            rmax = fmaxf(rmax, __shfl_xor_sync(0xffffffffu, rmax, 1));
            rmax = fmaxf(rmax, __shfl_xor_sync(0xffffffffu, rmax, 2));
            float newm = fmaxf(m, rmax);
            float alpha = __expf(m - newm);
            m = newm;
            ull ad = pk2(alpha, alpha);
#pragma unroll
            for (int i = 0; i < 8; i++) mul2(oacc[i], oacc[i], ad);

            float rsum = 0.0f;
#pragma unroll
            for (int jj = 0; jj < 16; jj += 4) {
                float4 s = *reinterpret_cast<const float4*>(&srow[jj]);
                s.x = __expf(s.x - newm); s.y = __expf(s.y - newm);
                s.z = __expf(s.z - newm); s.w = __expf(s.w - newm);
                *reinterpret_cast<float4*>(&srow[jj]) = s;
                rsum += (s.x + s.y) + (s.z + s.w);
            }
            rsum += __shfl_xor_sync(0xffffffffu, rsum, 1);
            rsum += __shfl_xor_sync(0xffffffffu, rsum, 2);
            l = l * alpha + rsum;
        }
        __syncwarp();

        // PV: oacc[row lr][cols lc..lc+15] += p[lr][j] * V[j][cols]
        {
            const float* prow = &Ss[lr * SS_STRIDE];
#pragma unroll 4
            for (int j = 0; j < 64; j++) {
                float p = prow[j];
                ull pd = pk2(p, p);
                const float4* v4 = reinterpret_cast<const float4*>(&Vs[j * 64 + lc]);
#pragma unroll
                for (int i = 0; i < 4; i++) {
                    float4 vv = v4[i];
                    ull vp0 = pk2(vv.x, vv.y);
                    ull vp1 = pk2(vv.z, vv.w);
                    fma2(oacc[2 * i + 0], pd, vp0);
                    fma2(oacc[2 * i + 1], pd, vp1);
                }
            }
        }
        __syncthreads();
    }

    float inv = 1.0f / l;
    float* dst = o + base + (size_t)(qt * 64 + lr) * D_MODEL + lc;
#pragma unroll
    for (int i = 0; i < 4; i++) {
        float2 p0 = upk2(oacc[2 * i + 0]);
        float2 p1 = upk2(oacc[2 * i + 1]);
        float4 ov = make_float4(p0.x * inv, p0.y * inv, p1.x * inv, p1.y * inv);
        reinterpret_cast<float4*>(dst)[i] = ov;
    }
}

// ---------------- launch ---------------------------------------------------
extern "C" void kernel_launch(void* const* d_in, const int* in_sizes, int n_in,
                              void* d_out, int out_size) {
    const float* query = (const float*)d_in[0];
    const float* key_  = (const float*)d_in[1];
    const float* value = (const float*)d_in[2];
    const float* Wq = (const float*)d_in[3];
    const float* bq = (const float*)d_in[4];
    const float* Aq = (const float*)d_in[5];
    const float* Wk = (const float*)d_in[6];
    const float* bk = (const float*)d_in[7];
    const float* Ak = (const float*)d_in[8];
    const float* Wv = (const float*)d_in[9];
    const float* bv = (const float*)d_in[10];
    const float* Av = (const float*)d_in[11];
    const float* Wo = (const float*)d_in[12];
    const float* bo = (const float*)d_in[13];
    float* out = (float*)d_out;

    float *pMq, *pMk, *pMv, *pMo, *pq, *pk, *pv, *pao;
    cudaGetSymbolAddress((void**)&pMq, g_Mq);
    cudaGetSymbolAddress((void**)&pMk, g_Mk);
    cudaGetSymbolAddress((void**)&pMv, g_Mv);
    cudaGetSymbolAddress((void**)&pMo, g_Mo);
    cudaGetSymbolAddress((void**)&pq, g_q);
    cudaGetSymbolAddress((void**)&pk, g_k);
    cudaGetSymbolAddress((void**)&pv, g_v);
    cudaGetSymbolAddress((void**)&pao, g_ao);

    cudaFuncSetAttribute(attn_kernel,
                         cudaFuncAttributeMaxDynamicSharedMemorySize, ATT_SMEM);

    int nw = D_MODEL * D_MODEL;
    int gb = (nw + 255) / 256;
    build_weight_kernel<<<gb, 256>>>(Wq, Aq, LORA_SCALE, pMq);
    build_weight_kernel<<<gb, 256>>>(Wk, Ak, LORA_SCALE, pMk);
    build_weight_kernel<<<gb, 256>>>(Wv, Av, LORA_SCALE, pMv);
    build_weight_kernel<<<gb, 256>>>(Wo, Aq, 0.0f, pMo);   // plain transpose

    dim3 ggrid(D_MODEL / 128, NTOK / 128);   // (6, 32)
    sgemm_bias_kernel<<<ggrid, 256>>>(query, pMq, bq, pq);
    sgemm_bias_kernel<<<ggrid, 256>>>(key_,  pMk, bk, pk);
    sgemm_bias_kernel<<<ggrid, 256>>>(value, pMv, bv, pv);

    dim3 agrid(SEQ / 64, 2 * NHEAD);         // (32, 24)
    attn_kernel<<<agrid, 256, ATT_SMEM>>>(pq, pk, pv, pao);

    sgemm_bias_kernel<<<ggrid, 256>>>(pao, pMo, bo, out);
}